// round 2
// baseline (speedup 1.0000x reference)
#include <cuda_runtime.h>

// Problem constants
#define BB 2
#define LL 512
#define DD 1024
#define HH 16
#define HDIM 64
#define MM 16384
#define TK 8
#define NROW (BB*LL)          // 1024
#define NQ   (BB*LL*HH)       // 16384
#define SCALE 0.125f          // 1/sqrt(64)

// Scratch (static device globals — no allocation allowed)
__device__ float g_q [BB*LL*DD];
__device__ float g_k [BB*LL*DD];
__device__ float g_v [BB*LL*DD];
__device__ float g_ao[BB*LL*DD];
__device__ int   g_idx[NQ*TK];

// ---------------------------------------------------------------------------
// GEMM: C[i,j] = sum_d X[i,d]*W[j,d] + bias[j]   (1024 x 1024 x 1024)
// BM=BN=64, BK=32, 256 threads, 4x4 microtile
// ---------------------------------------------------------------------------
__device__ __forceinline__ void gemm_tile(const float* __restrict__ X,
                                          const float* __restrict__ W,
                                          const float* __restrict__ bias,
                                          float* __restrict__ C,
                                          int bx, int by) {
    __shared__ __align__(16) float Xs[32][68];
    __shared__ __align__(16) float Ws[32][68];
    const int t  = threadIdx.x;        // 0..255
    const int tx = t & 15;
    const int ty = t >> 4;
    const int i0 = by * 64;
    const int j0 = bx * 64;
    float acc[4][4] = {};
    for (int k0 = 0; k0 < DD; k0 += 32) {
        #pragma unroll
        for (int j = 0; j < 2; ++j) {
            int f   = t + 256 * j;     // 0..511
            int row = f >> 3;          // 0..63
            int q   = f & 7;           // quad 0..7
            float4 xv = *(const float4*)(X + (size_t)(i0 + row) * DD + k0 + q * 4);
            Xs[q*4+0][row] = xv.x; Xs[q*4+1][row] = xv.y;
            Xs[q*4+2][row] = xv.z; Xs[q*4+3][row] = xv.w;
            float4 wv = *(const float4*)(W + (size_t)(j0 + row) * DD + k0 + q * 4);
            Ws[q*4+0][row] = wv.x; Ws[q*4+1][row] = wv.y;
            Ws[q*4+2][row] = wv.z; Ws[q*4+3][row] = wv.w;
        }
        __syncthreads();
        #pragma unroll
        for (int kk = 0; kk < 32; ++kk) {
            float4 a4 = *(const float4*)&Xs[kk][ty * 4];
            float4 b4 = *(const float4*)&Ws[kk][tx * 4];
            float a[4] = {a4.x, a4.y, a4.z, a4.w};
            float b[4] = {b4.x, b4.y, b4.z, b4.w};
            #pragma unroll
            for (int r = 0; r < 4; ++r)
                #pragma unroll
                for (int c = 0; c < 4; ++c)
                    acc[r][c] += a[r] * b[c];
        }
        __syncthreads();
    }
    #pragma unroll
    for (int r = 0; r < 4; ++r)
        #pragma unroll
        for (int c = 0; c < 4; ++c) {
            int j = j0 + tx * 4 + c;
            C[(size_t)(i0 + ty * 4 + r) * DD + j] = acc[r][c] + bias[j];
        }
}

__global__ void __launch_bounds__(256) k_qkv_proj(
    const float* __restrict__ x,
    const float* __restrict__ Wq, const float* __restrict__ bq,
    const float* __restrict__ Wk, const float* __restrict__ bk,
    const float* __restrict__ Wv, const float* __restrict__ bv) {
    const float* W; const float* bias; float* C;
    if (blockIdx.z == 0)      { W = Wq; bias = bq; C = g_q; }
    else if (blockIdx.z == 1) { W = Wk; bias = bk; C = g_k; }
    else                      { W = Wv; bias = bv; C = g_v; }
    gemm_tile(x, W, bias, C, blockIdx.x, blockIdx.y);
}

__global__ void __launch_bounds__(256) k_out_proj(
    const float* __restrict__ Wo, const float* __restrict__ bo,
    float* __restrict__ out) {
    gemm_tile(g_ao, Wo, bo, out, blockIdx.x, blockIdx.y);
}

// ---------------------------------------------------------------------------
// sim + top-k: for each flat query g (16384), top-8 over 16384 memory keys.
// Block = 256 threads = 64 queries x 4 key-subsets. Keys staged in smem
// (128-row chunks), query held in 64 registers, broadcast LDS reads.
// ---------------------------------------------------------------------------
__device__ __forceinline__ float dot4(float4 a, float4 b) {
    return a.x*b.x + a.y*b.y + a.z*b.z + a.w*b.w;
}

__global__ void __launch_bounds__(256) k_sim_topk(const float* __restrict__ mk) {
    __shared__ __align__(16) float smem[8192];     // 32 KB, reused
    float4* sk = (float4*)smem;                    // [128 rows][16 float4]

    const int t  = threadIdx.x;
    const int ql = t & 63;
    const int ks = t >> 6;                         // 0..3
    const int qg = blockIdx.x * 64 + ql;

    const float4* q4  = (const float4*)g_q;
    const float4* mk4 = (const float4*)mk;

    float4 qr[16];
    #pragma unroll
    for (int u = 0; u < 16; ++u) qr[u] = q4[(size_t)qg * 16 + u];

    float tv[8]; int ti[8];
    #pragma unroll
    for (int j = 0; j < 8; ++j) { tv[j] = -1e30f; ti[j] = 0; }

    for (int c = 0; c < MM / 128; ++c) {
        const int base = c * 128;
        #pragma unroll
        for (int j = 0; j < 8; ++j) {
            int f = t + 256 * j;                   // 0..2047
            sk[f] = mk4[(size_t)base * 16 + f];
        }
        __syncthreads();
        for (int kk = 0; kk < 32; ++kk) {
            int r = ks * 32 + kk;
            const float4* kp = sk + r * 16;
            float a0 = 0.f, a1 = 0.f, a2 = 0.f, a3 = 0.f;
            #pragma unroll
            for (int u = 0; u < 16; u += 4) {
                a0 += dot4(qr[u+0], kp[u+0]);
                a1 += dot4(qr[u+1], kp[u+1]);
                a2 += dot4(qr[u+2], kp[u+2]);
                a3 += dot4(qr[u+3], kp[u+3]);
            }
            float v = (a0 + a1) + (a2 + a3);
            if (v > tv[7]) {                       // rare
                tv[7] = v; ti[7] = base + r;
                #pragma unroll
                for (int j = 7; j > 0; --j) {
                    if (tv[j] > tv[j-1]) {
                        float fv = tv[j]; tv[j] = tv[j-1]; tv[j-1] = fv;
                        int   iv = ti[j]; ti[j] = ti[j-1]; ti[j-1] = iv;
                    }
                }
            }
        }
        __syncthreads();
    }

    // merge 4 sorted runs of 8 per query (reuse smem)
    float* mbv = smem;                 // 64*32 floats
    int*   mbi = (int*)(smem + 2048);  // 64*32 ints
    #pragma unroll
    for (int j = 0; j < 8; ++j) {
        mbv[ql * 32 + ks * 8 + j] = tv[j];
        mbi[ql * 32 + ks * 8 + j] = ti[j];
    }
    __syncthreads();
    if (ks == 0) {
        int p[4] = {0, 0, 0, 0};
        const int base = ql * 32;
        for (int o = 0; o < TK; ++o) {
            float best = -1e38f; int bs = 0;
            #pragma unroll
            for (int s = 0; s < 4; ++s) {
                float cand = (p[s] < 8) ? mbv[base + s * 8 + p[s]] : -1e38f;
                if (cand > best) { best = cand; bs = s; }
            }
            g_idx[qg * TK + o] = mbi[base + bs * 8 + p[bs]];
            p[bs]++;
        }
    }
}

// ---------------------------------------------------------------------------
// Flash attention over [gathered memory prefix (4096) | causal local (512)].
// Block = 64 queries x 2 key-split threads = 128 threads.
// grid = (8 q-tiles, 16 heads, 2 batch)
// ---------------------------------------------------------------------------
__global__ void __launch_bounds__(128) k_attn(const float* __restrict__ mk,
                                              const float* __restrict__ mv) {
    __shared__ __align__(16) float4 kb[64 * 16];   // 16 KB
    __shared__ __align__(16) float4 vb[64 * 16];   // 16 KB
    __shared__ float sm[64], sl[64];

    const int t    = threadIdx.x;
    const int ql   = t & 63;
    const int half = t >> 6;                       // 0 or 1
    const int qt   = blockIdx.x;                   // 0..7
    const int h    = blockIdx.y;
    const int b    = blockIdx.z;
    const int i    = qt * 64 + ql;                 // query position in L
    const int qg   = (b * LL + i) * HH + h;        // flat (b,l,h)

    const float4* q4  = (const float4*)g_q;
    const float4* mk4 = (const float4*)mk;
    const float4* mv4 = (const float4*)mv;
    const float4* k4  = (const float4*)g_k;
    const float4* v4  = (const float4*)g_v;

    float4 qr[16];
    #pragma unroll
    for (int u = 0; u < 16; ++u) qr[u] = q4[(size_t)qg * 16 + u];

    float4 acc[16];
    #pragma unroll
    for (int u = 0; u < 16; ++u) acc[u] = make_float4(0.f, 0.f, 0.f, 0.f);
    float m = -1e30f, l = 0.f;

    // ---- memory-prefix phase: 4096 gathered slots, 64 chunks of 64 ----
    for (int c = 0; c < 64; ++c) {
        #pragma unroll
        for (int j = 0; j < 8; ++j) {
            int f = t + 128 * j;                   // 0..1023
            int row = f >> 4, quad = f & 15;
            int p = c * 64 + row;                  // prefix position
            int mi = g_idx[((b * LL + (p >> 3)) * HH + h) * TK + (p & 7)];
            kb[f] = mk4[(size_t)mi * 16 + quad];
            vb[f] = mv4[(size_t)mi * 16 + quad];
        }
        __syncthreads();
        for (int kk = 0; kk < 32; ++kk) {
            int r = half * 32 + kk;
            const float4* kp = kb + r * 16;
            float a0 = 0.f, a1 = 0.f, a2 = 0.f, a3 = 0.f;
            #pragma unroll
            for (int u = 0; u < 16; u += 4) {
                a0 += dot4(qr[u+0], kp[u+0]);
                a1 += dot4(qr[u+1], kp[u+1]);
                a2 += dot4(qr[u+2], kp[u+2]);
                a3 += dot4(qr[u+3], kp[u+3]);
            }
            float s = ((a0 + a1) + (a2 + a3)) * SCALE;
            if (s > m) {
                float corr = __expf(m - s);
                m = s; l *= corr;
                #pragma unroll
                for (int u = 0; u < 16; ++u) {
                    acc[u].x *= corr; acc[u].y *= corr;
                    acc[u].z *= corr; acc[u].w *= corr;
                }
            }
            float p = __expf(s - m);
            l += p;
            const float4* vp = vb + r * 16;
            #pragma unroll
            for (int u = 0; u < 16; ++u) {
                float4 vv = vp[u];
                acc[u].x += p * vv.x; acc[u].y += p * vv.y;
                acc[u].z += p * vv.z; acc[u].w += p * vv.w;
            }
        }
        __syncthreads();
    }

    // ---- local causal phase: chunks 0..qt ----
    for (int c = 0; c <= qt; ++c) {
        #pragma unroll
        for (int j = 0; j < 8; ++j) {
            int f = t + 128 * j;
            int row = f >> 4, quad = f & 15;
            int jl = c * 64 + row;
            size_t rg = (size_t)((b * LL + jl) * HH + h);
            kb[f] = k4[rg * 16 + quad];
            vb[f] = v4[rg * 16 + quad];
        }
        __syncthreads();
        const bool edge = (c == qt);
        for (int kk = 0; kk < 32; ++kk) {
            int r = half * 32 + kk;
            int jl = c * 64 + r;
            if (edge && jl > i) continue;          // causal mask
            const float4* kp = kb + r * 16;
            float a0 = 0.f, a1 = 0.f, a2 = 0.f, a3 = 0.f;
            #pragma unroll
            for (int u = 0; u < 16; u += 4) {
                a0 += dot4(qr[u+0], kp[u+0]);
                a1 += dot4(qr[u+1], kp[u+1]);
                a2 += dot4(qr[u+2], kp[u+2]);
                a3 += dot4(qr[u+3], kp[u+3]);
            }
            float s = ((a0 + a1) + (a2 + a3)) * SCALE;
            if (s > m) {
                float corr = __expf(m - s);
                m = s; l *= corr;
                #pragma unroll
                for (int u = 0; u < 16; ++u) {
                    acc[u].x *= corr; acc[u].y *= corr;
                    acc[u].z *= corr; acc[u].w *= corr;
                }
            }
            float p = __expf(s - m);
            l += p;
            const float4* vp = vb + r * 16;
            #pragma unroll
            for (int u = 0; u < 16; ++u) {
                float4 vv = vp[u];
                acc[u].x += p * vv.x; acc[u].y += p * vv.y;
                acc[u].z += p * vv.z; acc[u].w += p * vv.w;
            }
        }
        __syncthreads();
    }

    // ---- merge the two key-split halves, normalize, write ----
    __syncthreads();
    float4* sacc = kb;                             // reuse 16 KB
    if (half == 1) {
        sm[ql] = m; sl[ql] = l;
        #pragma unroll
        for (int u = 0; u < 16; ++u) sacc[ql * 16 + u] = acc[u];
    }
    __syncthreads();
    if (half == 0) {
        float m1 = sm[ql], l1 = sl[ql];
        float mf = fmaxf(m, m1);
        float c0 = __expf(m - mf), c1 = __expf(m1 - mf);
        float inv = 1.f / (l * c0 + l1 * c1);
        float4* ao4 = (float4*)g_ao;
        #pragma unroll
        for (int u = 0; u < 16; ++u) {
            float4 a1 = sacc[ql * 16 + u];
            float4 o;
            o.x = (acc[u].x * c0 + a1.x * c1) * inv;
            o.y = (acc[u].y * c0 + a1.y * c1) * inv;
            o.z = (acc[u].z * c0 + a1.z * c1) * inv;
            o.w = (acc[u].w * c0 + a1.w * c1) * inv;
            ao4[(size_t)qg * 16 + u] = o;
        }
    }
}

// ---------------------------------------------------------------------------
extern "C" void kernel_launch(void* const* d_in, const int* in_sizes, int n_in,
                              void* d_out, int out_size) {
    const float* x          = (const float*)d_in[0];
    const float* mem_keys   = (const float*)d_in[1];
    const float* mem_values = (const float*)d_in[2];
    const float* Wq = (const float*)d_in[3];
    const float* bq = (const float*)d_in[4];
    const float* Wk = (const float*)d_in[5];
    const float* bk = (const float*)d_in[6];
    const float* Wv = (const float*)d_in[7];
    const float* bv = (const float*)d_in[8];
    const float* Wo = (const float*)d_in[9];
    const float* bo = (const float*)d_in[10];
    float* out = (float*)d_out;

    k_qkv_proj<<<dim3(16, 16, 3), 256>>>(x, Wq, bq, Wk, bk, Wv, bv);
    k_sim_topk<<<NQ / 64, 256>>>(mem_keys);
    k_attn<<<dim3(8, 16, 2), 128>>>(mem_keys, mem_values);
    k_out_proj<<<dim3(16, 16, 1), 256>>>(Wo, bo, out);
}

// round 3
// speedup vs baseline: 1.2909x; 1.2909x over previous
#include <cuda_runtime.h>

// Problem constants
#define BB 2
#define LL 512
#define DD 1024
#define HH 16
#define HDIM 64
#define MM 16384
#define TK 8
#define NROW (BB*LL)          // 1024
#define NQ   (BB*LL*HH)       // 16384
#define SCALE 0.125f          // 1/sqrt(64)

typedef unsigned long long u64;

// Packed fp32x2 helpers (Blackwell FFMA2 path — ptxas won't auto-fuse)
__device__ __forceinline__ u64 pk2(float x, float y) {
    u64 r; asm("mov.b64 %0, {%1,%2};" : "=l"(r) : "f"(x), "f"(y)); return r;
}
__device__ __forceinline__ float2 upk2(u64 a) {
    float2 f; asm("mov.b64 {%0,%1}, %2;" : "=f"(f.x), "=f"(f.y) : "l"(a)); return f;
}
__device__ __forceinline__ u64 fma2(u64 a, u64 b, u64 c) {
    u64 d; asm("fma.rn.f32x2 %0, %1, %2, %3;" : "=l"(d) : "l"(a), "l"(b), "l"(c)); return d;
}
__device__ __forceinline__ u64 mul2(u64 a, u64 b) {
    u64 d; asm("mul.rn.f32x2 %0, %1, %2;" : "=l"(d) : "l"(a), "l"(b)); return d;
}

// Scratch (static device globals — no allocation allowed)
__device__ float g_q [BB*LL*DD];
__device__ float g_k [BB*LL*DD];
__device__ float g_v [BB*LL*DD];
__device__ float g_ao[BB*LL*DD];
__device__ int   g_idx[NQ*TK];

// ---------------------------------------------------------------------------
// GEMM: C[i,j] = sum_d X[i,d]*W[j,d] + bias[j]   (1024 x 1024 x 1024)
// BM=BN=64, BK=32, 256 threads, 4x4 microtile, f32x2 inner product
// ---------------------------------------------------------------------------
__device__ __forceinline__ void gemm_tile(const float* __restrict__ X,
                                          const float* __restrict__ W,
                                          const float* __restrict__ bias,
                                          float* __restrict__ C,
                                          int bx, int by) {
    __shared__ __align__(16) float Xs[32][68];
    __shared__ __align__(16) float Ws[32][68];
    const int t  = threadIdx.x;        // 0..255
    const int tx = t & 15;
    const int ty = t >> 4;
    const int i0 = by * 64;
    const int j0 = bx * 64;
    u64 acc2[4][2];
    #pragma unroll
    for (int r = 0; r < 4; ++r) { acc2[r][0] = 0ull; acc2[r][1] = 0ull; }

    for (int k0 = 0; k0 < DD; k0 += 32) {
        #pragma unroll
        for (int j = 0; j < 2; ++j) {
            int f   = t + 256 * j;     // 0..511
            int row = f >> 3;          // 0..63
            int q   = f & 7;           // quad 0..7
            float4 xv = *(const float4*)(X + (size_t)(i0 + row) * DD + k0 + q * 4);
            Xs[q*4+0][row] = xv.x; Xs[q*4+1][row] = xv.y;
            Xs[q*4+2][row] = xv.z; Xs[q*4+3][row] = xv.w;
            float4 wv = *(const float4*)(W + (size_t)(j0 + row) * DD + k0 + q * 4);
            Ws[q*4+0][row] = wv.x; Ws[q*4+1][row] = wv.y;
            Ws[q*4+2][row] = wv.z; Ws[q*4+3][row] = wv.w;
        }
        __syncthreads();
        #pragma unroll
        for (int kk = 0; kk < 32; ++kk) {
            float4 a4 = *(const float4*)&Xs[kk][ty * 4];
            ulonglong2 b2 = *(const ulonglong2*)&Ws[kk][tx * 4];
            u64 ad0 = pk2(a4.x, a4.x);
            u64 ad1 = pk2(a4.y, a4.y);
            u64 ad2 = pk2(a4.z, a4.z);
            u64 ad3 = pk2(a4.w, a4.w);
            acc2[0][0] = fma2(ad0, b2.x, acc2[0][0]);
            acc2[0][1] = fma2(ad0, b2.y, acc2[0][1]);
            acc2[1][0] = fma2(ad1, b2.x, acc2[1][0]);
            acc2[1][1] = fma2(ad1, b2.y, acc2[1][1]);
            acc2[2][0] = fma2(ad2, b2.x, acc2[2][0]);
            acc2[2][1] = fma2(ad2, b2.y, acc2[2][1]);
            acc2[3][0] = fma2(ad3, b2.x, acc2[3][0]);
            acc2[3][1] = fma2(ad3, b2.y, acc2[3][1]);
        }
        __syncthreads();
    }
    #pragma unroll
    for (int r = 0; r < 4; ++r) {
        float2 c01 = upk2(acc2[r][0]);
        float2 c23 = upk2(acc2[r][1]);
        int j = j0 + tx * 4;
        float* cp = C + (size_t)(i0 + ty * 4 + r) * DD + j;
        cp[0] = c01.x + bias[j + 0];
        cp[1] = c01.y + bias[j + 1];
        cp[2] = c23.x + bias[j + 2];
        cp[3] = c23.y + bias[j + 3];
    }
}

__global__ void __launch_bounds__(256) k_qkv_proj(
    const float* __restrict__ x,
    const float* __restrict__ Wq, const float* __restrict__ bq,
    const float* __restrict__ Wk, const float* __restrict__ bk,
    const float* __restrict__ Wv, const float* __restrict__ bv) {
    const float* W; const float* bias; float* C;
    if (blockIdx.z == 0)      { W = Wq; bias = bq; C = g_q; }
    else if (blockIdx.z == 1) { W = Wk; bias = bk; C = g_k; }
    else                      { W = Wv; bias = bv; C = g_v; }
    gemm_tile(x, W, bias, C, blockIdx.x, blockIdx.y);
}

__global__ void __launch_bounds__(256) k_out_proj(
    const float* __restrict__ Wo, const float* __restrict__ bo,
    float* __restrict__ out) {
    gemm_tile(g_ao, Wo, bo, out, blockIdx.x, blockIdx.y);
}

// ---------------------------------------------------------------------------
// Packed 64-dim dot product: q (32 x u64 regs) . k (smem row as ulonglong2*)
// ---------------------------------------------------------------------------
__device__ __forceinline__ float dot64_f32x2(const u64* __restrict__ qc,
                                             const ulonglong2* __restrict__ kp) {
    u64 a0 = 0ull, a1 = 0ull, a2 = 0ull, a3 = 0ull;
    #pragma unroll
    for (int u = 0; u < 16; u += 4) {
        ulonglong2 k0 = kp[u + 0];
        ulonglong2 k1 = kp[u + 1];
        ulonglong2 k2 = kp[u + 2];
        ulonglong2 k3 = kp[u + 3];
        a0 = fma2(qc[2*u + 0], k0.x, a0);
        a1 = fma2(qc[2*u + 1], k0.y, a1);
        a2 = fma2(qc[2*u + 2], k1.x, a2);
        a3 = fma2(qc[2*u + 3], k1.y, a3);
        a0 = fma2(qc[2*u + 4], k2.x, a0);
        a1 = fma2(qc[2*u + 5], k2.y, a1);
        a2 = fma2(qc[2*u + 6], k3.x, a2);
        a3 = fma2(qc[2*u + 7], k3.y, a3);
    }
    float2 f0 = upk2(a0), f1 = upk2(a1), f2 = upk2(a2), f3 = upk2(a3);
    return ((f0.x + f0.y) + (f1.x + f1.y)) + ((f2.x + f2.y) + (f3.x + f3.y));
}

// ---------------------------------------------------------------------------
// sim + top-k: for each flat query g (16384), top-8 over 16384 memory keys.
// Block = 256 threads = 64 queries x 4 key-subsets.
// ---------------------------------------------------------------------------
__global__ void __launch_bounds__(256) k_sim_topk(const float* __restrict__ mk) {
    __shared__ __align__(16) float smem[8192];     // 32 KB, reused
    float4* sk = (float4*)smem;                    // [128 rows][16 float4]

    const int t  = threadIdx.x;
    const int ql = t & 63;
    const int ks = t >> 6;                         // 0..3
    const int qg = blockIdx.x * 64 + ql;

    const float4* mk4 = (const float4*)mk;
    const ulonglong2* q2 = (const ulonglong2*)g_q;

    u64 qc[32];
    #pragma unroll
    for (int u = 0; u < 16; ++u) {
        ulonglong2 qv = q2[(size_t)qg * 16 + u];
        qc[2*u] = qv.x; qc[2*u + 1] = qv.y;
    }

    float tv[8]; int ti[8];
    #pragma unroll
    for (int j = 0; j < 8; ++j) { tv[j] = -1e30f; ti[j] = 0; }

    for (int c = 0; c < MM / 128; ++c) {
        const int base = c * 128;
        #pragma unroll
        for (int j = 0; j < 8; ++j) {
            int f = t + 256 * j;                   // 0..2047
            sk[f] = mk4[(size_t)base * 16 + f];
        }
        __syncthreads();
        for (int kk = 0; kk < 32; ++kk) {
            int r = ks * 32 + kk;
            float v = dot64_f32x2(qc, (const ulonglong2*)(sk + r * 16));
            if (v > tv[7]) {                       // rare
                tv[7] = v; ti[7] = base + r;
                #pragma unroll
                for (int j = 7; j > 0; --j) {
                    if (tv[j] > tv[j-1]) {
                        float fv = tv[j]; tv[j] = tv[j-1]; tv[j-1] = fv;
                        int   iv = ti[j]; ti[j] = ti[j-1]; ti[j-1] = iv;
                    }
                }
            }
        }
        __syncthreads();
    }

    // merge 4 sorted runs of 8 per query (reuse smem)
    float* mbv = smem;                 // 64*32 floats
    int*   mbi = (int*)(smem + 2048);  // 64*32 ints
    #pragma unroll
    for (int j = 0; j < 8; ++j) {
        mbv[ql * 32 + ks * 8 + j] = tv[j];
        mbi[ql * 32 + ks * 8 + j] = ti[j];
    }
    __syncthreads();
    if (ks == 0) {
        int p[4] = {0, 0, 0, 0};
        const int base = ql * 32;
        for (int o = 0; o < TK; ++o) {
            float best = -1e38f; int bs = 0;
            #pragma unroll
            for (int s = 0; s < 4; ++s) {
                float cand = (p[s] < 8) ? mbv[base + s * 8 + p[s]] : -1e38f;
                if (cand > best) { best = cand; bs = s; }
            }
            g_idx[qg * TK + o] = mbi[base + bs * 8 + p[bs]];
            p[bs]++;
        }
    }
}

// ---------------------------------------------------------------------------
// Flash attention over [gathered memory prefix (4096) | causal local (512)].
// Block = 64 queries x 2 key-split threads = 128 threads.
// grid = (8 q-tiles, 16 heads, 2 batch)
// ---------------------------------------------------------------------------
__global__ void __launch_bounds__(128) k_attn(const float* __restrict__ mk,
                                              const float* __restrict__ mv) {
    __shared__ __align__(16) float4 kb[64 * 16];   // 16 KB
    __shared__ __align__(16) float4 vb[64 * 16];   // 16 KB
    __shared__ float sm[64], sl[64];

    const int t    = threadIdx.x;
    const int ql   = t & 63;
    const int half = t >> 6;                       // 0 or 1
    const int qt   = blockIdx.x;                   // 0..7
    const int h    = blockIdx.y;
    const int b    = blockIdx.z;
    const int i    = qt * 64 + ql;                 // query position in L
    const int qg   = (b * LL + i) * HH + h;        // flat (b,l,h)

    const float4* mk4 = (const float4*)mk;
    const float4* mv4 = (const float4*)mv;
    const float4* k4  = (const float4*)g_k;
    const float4* v4  = (const float4*)g_v;
    const ulonglong2* q2 = (const ulonglong2*)g_q;

    u64 qc[32];
    #pragma unroll
    for (int u = 0; u < 16; ++u) {
        ulonglong2 qv = q2[(size_t)qg * 16 + u];
        qc[2*u] = qv.x; qc[2*u + 1] = qv.y;
    }

    u64 acc2[32];
    #pragma unroll
    for (int u = 0; u < 32; ++u) acc2[u] = 0ull;
    float m = -1e30f, l = 0.f;

    // ---- memory-prefix phase: 4096 gathered slots, 64 chunks of 64 ----
    for (int c = 0; c < 64; ++c) {
        #pragma unroll
        for (int j = 0; j < 8; ++j) {
            int f = t + 128 * j;                   // 0..1023
            int row = f >> 4, quad = f & 15;
            int p = c * 64 + row;                  // prefix position
            int mi = g_idx[((b * LL + (p >> 3)) * HH + h) * TK + (p & 7)];
            kb[f] = mk4[(size_t)mi * 16 + quad];
            vb[f] = mv4[(size_t)mi * 16 + quad];
        }
        __syncthreads();
        for (int kk = 0; kk < 32; ++kk) {
            int r = half * 32 + kk;
            float s = dot64_f32x2(qc, (const ulonglong2*)(kb + r * 16)) * SCALE;
            if (s > m) {
                float corr = __expf(m - s);
                m = s; l *= corr;
                u64 cd = pk2(corr, corr);
                #pragma unroll
                for (int u = 0; u < 32; ++u) acc2[u] = mul2(acc2[u], cd);
            }
            float p = __expf(s - m);
            l += p;
            u64 pd = pk2(p, p);
            const ulonglong2* vp = (const ulonglong2*)(vb + r * 16);
            #pragma unroll
            for (int u = 0; u < 16; ++u) {
                ulonglong2 vv = vp[u];
                acc2[2*u]     = fma2(pd, vv.x, acc2[2*u]);
                acc2[2*u + 1] = fma2(pd, vv.y, acc2[2*u + 1]);
            }
        }
        __syncthreads();
    }

    // ---- local causal phase: chunks 0..qt ----
    for (int c = 0; c <= qt; ++c) {
        #pragma unroll
        for (int j = 0; j < 8; ++j) {
            int f = t + 128 * j;
            int row = f >> 4, quad = f & 15;
            int jl = c * 64 + row;
            size_t rg = (size_t)((b * LL + jl) * HH + h);
            kb[f] = k4[rg * 16 + quad];
            vb[f] = v4[rg * 16 + quad];
        }
        __syncthreads();
        const bool edge = (c == qt);
        for (int kk = 0; kk < 32; ++kk) {
            int r = half * 32 + kk;
            int jl = c * 64 + r;
            if (edge && jl > i) continue;          // causal mask
            float s = dot64_f32x2(qc, (const ulonglong2*)(kb + r * 16)) * SCALE;
            if (s > m) {
                float corr = __expf(m - s);
                m = s; l *= corr;
                u64 cd = pk2(corr, corr);
                #pragma unroll
                for (int u = 0; u < 32; ++u) acc2[u] = mul2(acc2[u], cd);
            }
            float p = __expf(s - m);
            l += p;
            u64 pd = pk2(p, p);
            const ulonglong2* vp = (const ulonglong2*)(vb + r * 16);
            #pragma unroll
            for (int u = 0; u < 16; ++u) {
                ulonglong2 vv = vp[u];
                acc2[2*u]     = fma2(pd, vv.x, acc2[2*u]);
                acc2[2*u + 1] = fma2(pd, vv.y, acc2[2*u + 1]);
            }
        }
        __syncthreads();
    }

    // ---- merge the two key-split halves, normalize, write ----
    __syncthreads();
    u64* sacc = (u64*)kb;                          // reuse 16 KB (need 16KB exactly)
    if (half == 1) {
        sm[ql] = m; sl[ql] = l;
        #pragma unroll
        for (int u = 0; u < 32; ++u) sacc[ql * 32 + u] = acc2[u];
    }
    __syncthreads();
    if (half == 0) {
        float m1 = sm[ql], l1 = sl[ql];
        float mf = fmaxf(m, m1);
        float c0 = __expf(m - mf), c1 = __expf(m1 - mf);
        float inv = 1.f / (l * c0 + l1 * c1);
        float2* ao2 = (float2*)g_ao;
        #pragma unroll
        for (int u = 0; u < 32; ++u) {
            float2 a0 = upk2(acc2[u]);
            float2 a1 = upk2(sacc[ql * 32 + u]);
            float2 o;
            o.x = (a0.x * c0 + a1.x * c1) * inv;
            o.y = (a0.y * c0 + a1.y * c1) * inv;
            ao2[(size_t)qg * 32 + u] = o;
        }
    }
}

// ---------------------------------------------------------------------------
extern "C" void kernel_launch(void* const* d_in, const int* in_sizes, int n_in,
                              void* d_out, int out_size) {
    const float* x          = (const float*)d_in[0];
    const float* mem_keys   = (const float*)d_in[1];
    const float* mem_values = (const float*)d_in[2];
    const float* Wq = (const float*)d_in[3];
    const float* bq = (const float*)d_in[4];
    const float* Wk = (const float*)d_in[5];
    const float* bk = (const float*)d_in[6];
    const float* Wv = (const float*)d_in[7];
    const float* bv = (const float*)d_in[8];
    const float* Wo = (const float*)d_in[9];
    const float* bo = (const float*)d_in[10];
    float* out = (float*)d_out;

    k_qkv_proj<<<dim3(16, 16, 3), 256>>>(x, Wq, bq, Wk, bk, Wv, bv);
    k_sim_topk<<<NQ / 64, 256>>>(mem_keys);
    k_attn<<<dim3(8, 16, 2), 128>>>(mem_keys, mem_values);
    k_out_proj<<<dim3(16, 16, 1), 256>>>(Wo, bo, out);
}